// round 6
// baseline (speedup 1.0000x reference)
#include <cuda_runtime.h>
#include <cstddef>

// Problem constants (fixed by setup_inputs)
constexpr int D      = 64;
constexpr int N      = 128;
constexpr int NSTEPS = 16;

// ---------------- device scratch (no allocations allowed) ----------------
__device__ __align__(16) float g_R[NSTEPS][D * D];  // [s][i*64+a] = R_{15-s}[a][i]
__device__ __align__(16) float g_X[NSTEPS][N * D];  // x_s, s = 0..15

// KPREP: direct row-wise simulation of BOTH systems in one launch.
//   rows 0..127   : state rows (x0, v0)            -> g_X[t], traj frames
//   rows 128..191 : propagator rows a = row-128,
//                   X0 = dt^2*e_a, V0 = dt*e_a     -> X_k = R_k, stored transposed
// One warp per row; lane owns 2 columns; M columns live in registers.
// M[k][c] = W[c][k] - delta(k,c)  (row-vector convention: f = x*M).
__global__ void __launch_bounds__(128) kprep(const float* __restrict__ x0,
                                             const float* __restrict__ v0,
                                             const float* __restrict__ W,
                                             float* __restrict__ out) {
    __shared__ float sX[4][D];
    const int tid = threadIdx.x;
    const int w   = tid >> 5;                  // warp = local row
    const int l   = tid & 31;
    const int row = blockIdx.x * 4 + w;        // 0..191
    const int c0  = 2 * l;
    const float dt = 0.01f;
    const bool is_state = (row < N);
    const int a = row - N;                     // propagator row index (if !is_state)

    // Load this lane's two M columns into registers (fully unrolled).
    float mA[D], mB[D];
    {
        const float4* wa = (const float4*)(W + (size_t)c0 * D);
        const float4* wb = (const float4*)(W + (size_t)(c0 + 1) * D);
#pragma unroll
        for (int q = 0; q < 16; q++) {
            float4 va = wa[q], vb = wb[q];
            const int k = 4 * q;
            mA[k+0] = va.x - ((k+0) == c0     ? 1.0f : 0.0f);
            mA[k+1] = va.y - ((k+1) == c0     ? 1.0f : 0.0f);
            mA[k+2] = va.z - ((k+2) == c0     ? 1.0f : 0.0f);
            mA[k+3] = va.w - ((k+3) == c0     ? 1.0f : 0.0f);
            mB[k+0] = vb.x - ((k+0) == c0 + 1 ? 1.0f : 0.0f);
            mB[k+1] = vb.y - ((k+1) == c0 + 1 ? 1.0f : 0.0f);
            mB[k+2] = vb.z - ((k+2) == c0 + 1 ? 1.0f : 0.0f);
            mB[k+3] = vb.w - ((k+3) == c0 + 1 ? 1.0f : 0.0f);
        }
    }

    // Initial state for this lane's two columns.
    float2 xl, vl;
    if (is_state) {
        xl = *(const float2*)(x0 + (size_t)row * D + c0);
        vl = *(const float2*)(v0 + (size_t)row * D + c0);
    } else {
        xl = make_float2(c0 == a ? dt * dt : 0.0f, (c0 + 1) == a ? dt * dt : 0.0f);
        vl = make_float2(c0 == a ? dt      : 0.0f, (c0 + 1) == a ? dt      : 0.0f);
    }

    // t = 0 outputs.
    if (is_state) {
        *(float2*)&g_X[0][row * D + c0] = xl;                 // x_0
        *(float2*)(out + (size_t)row * D + c0) = xl;          // traj frame 0
    } else {
        g_R[15][c0 * D + a]       = xl.x;                     // R_0 transposed
        g_R[15][(c0 + 1) * D + a] = xl.y;
    }

    *(float2*)&sX[w][c0] = xl;
    __syncwarp();

#pragma unroll 1
    for (int t = 1; t <= NSTEPS; t++) {
        // Two interleaved accumulator pairs: halves the serial FMA chain.
        float2 y0 = make_float2(0.0f, 0.0f);
        float2 y1 = make_float2(0.0f, 0.0f);
#pragma unroll
        for (int k = 0; k < D; k += 2) {
            float xk0 = sX[w][k], xk1 = sX[w][k + 1];
            y0.x += xk0 * mA[k];     y0.y += xk0 * mB[k];
            y1.x += xk1 * mA[k + 1]; y1.y += xk1 * mB[k + 1];
        }
        float2 y = make_float2(y0.x + y1.x, y0.y + y1.y);
        vl.x += dt * y.x;  vl.y += dt * y.y;
        xl.x += dt * vl.x; xl.y += dt * vl.y;
        __syncwarp();
        *(float2*)&sX[w][c0] = xl;
        __syncwarp();

        if (is_state) {
            if (t < NSTEPS)
                *(float2*)&g_X[t][row * D + c0] = xl;
            if ((t & 3) == 0) {
                float* o = out + (size_t)(t >> 2) * (N * D) + (size_t)row * D + c0;
                *(float2*)o = xl;
            }
        } else if (t < NSTEPS) {
            g_R[15 - t][c0 * D + a]       = xl.x;
            g_R[15 - t][(c0 + 1) * D + a] = xl.y;
        }
    }
}

__device__ __forceinline__ unsigned long long dup2(float f) {
    unsigned long long r;
    asm("mov.b64 %0, {%1, %1};" : "=l"(r) : "r"(__float_as_uint(f)));
    return r;
}

// K4: jac[n][i][a][b] = sum_s g_R[s][i][a] * g_X[s][n][b].
// Block covers (2 n) x (2 i) x 64a x 64b = 16384 outputs; thread does an 8x8
// tile using packed fma.rn.f32x2. R is staged in smem pre-duplicated into both
// b64 halves, so the inner loop is pure LDS.128 + FFMA2 (no movs).
__global__ void __launch_bounds__(256, 3) k4_jac(float* __restrict__ jac) {
    __shared__ __align__(16) unsigned long long sR2[NSTEPS][2][D];  // 16 KB
    __shared__ __align__(16) float sX[NSTEPS][2][D];                //  8 KB
    const int tid = threadIdx.x, bid = blockIdx.x;
    const int n0 = (bid >> 5) << 1;   // 0,2,..,126
    const int i0 = (bid & 31) << 1;   // 0,2,..,62

    // Fill: 512 float4 of X; R duplicated into b64 halves.
#pragma unroll
    for (int v = tid; v < 512; v += 256) {
        const int s  = v >> 5;
        const int il = (v >> 4) & 1;
        const int aa = (v & 15) << 2;
        float4 x = *(const float4*)&g_X[s][(n0 + il) * D + aa];
        float4 r = *(const float4*)&g_R[s][(i0 + il) * D + aa];
        *(float4*)&sX[s][il][aa] = x;
        *(ulonglong2*)&sR2[s][il][aa]     = make_ulonglong2(dup2(r.x), dup2(r.y));
        *(ulonglong2*)&sR2[s][il][aa + 2] = make_ulonglong2(dup2(r.z), dup2(r.w));
    }
    __syncthreads();

    const int nl  = (tid >> 7) & 1;
    const int il  = (tid >> 6) & 1;
    const int idx = tid & 63;
    const int a0  = (idx >> 3) << 3;
    const int b0  = (idx & 7) << 3;

    unsigned long long acc[8][4];
#pragma unroll
    for (int ia = 0; ia < 8; ia++)
#pragma unroll
        for (int jb = 0; jb < 4; jb++) acc[ia][jb] = 0ull;

#pragma unroll
    for (int s = 0; s < NSTEPS; s++) {
        // xb: 8 floats = 4 packed f32x2 (b is the packed lane pair)
        const ulonglong2 x01 = *(const ulonglong2*)&sX[s][nl][b0];
        const ulonglong2 x23 = *(const ulonglong2*)&sX[s][nl][b0 + 4];
        unsigned long long xb[4] = {x01.x, x01.y, x23.x, x23.y};
        // First half: ra[a0..a0+3] (pre-duplicated b64)
        {
            const ulonglong2 r01 = *(const ulonglong2*)&sR2[s][il][a0];
            const ulonglong2 r23 = *(const ulonglong2*)&sR2[s][il][a0 + 2];
            unsigned long long rr[4] = {r01.x, r01.y, r23.x, r23.y};
#pragma unroll
            for (int ia = 0; ia < 4; ia++)
#pragma unroll
                for (int jb = 0; jb < 4; jb++)
                    asm("fma.rn.f32x2 %0, %1, %2, %0;"
                        : "+l"(acc[ia][jb]) : "l"(rr[ia]), "l"(xb[jb]));
        }
        // Second half: ra[a0+4..a0+7]
        {
            const ulonglong2 r01 = *(const ulonglong2*)&sR2[s][il][a0 + 4];
            const ulonglong2 r23 = *(const ulonglong2*)&sR2[s][il][a0 + 6];
            unsigned long long rr[4] = {r01.x, r01.y, r23.x, r23.y};
#pragma unroll
            for (int ia = 0; ia < 4; ia++)
#pragma unroll
                for (int jb = 0; jb < 4; jb++)
                    asm("fma.rn.f32x2 %0, %1, %2, %0;"
                        : "+l"(acc[ia + 4][jb]) : "l"(rr[ia]), "l"(xb[jb]));
        }
    }

    const size_t base = (((size_t)(n0 + nl) * D + (i0 + il)) * D) * D;
#pragma unroll
    for (int ia = 0; ia < 8; ia++) {
        float* p = jac + base + (size_t)(a0 + ia) * D + b0;
        *(ulonglong2*)p       = make_ulonglong2(acc[ia][0], acc[ia][1]);
        *(ulonglong2*)(p + 4) = make_ulonglong2(acc[ia][2], acc[ia][3]);
    }
}

extern "C" void kernel_launch(void* const* d_in, const int* in_sizes, int n_in,
                              void* d_out, int out_size) {
    const float* x0 = (const float*)d_in[0];
    const float* v0 = (const float*)d_in[1];
    const float* W  = (const float*)d_in[2];
    float* out = (float*)d_out;
    // output = [traj (frames x N x D)] then [jac (N x D x D x D)]
    float* jac = out + ((size_t)out_size - (size_t)N * D * D * D);

    kprep<<<48, 128>>>(x0, v0, W, out);
    k4_jac<<<2048, 256>>>(jac);
}

// round 7
// speedup vs baseline: 1.2280x; 1.2280x over previous
#include <cuda_runtime.h>
#include <cstddef>

// Problem constants (fixed by setup_inputs)
constexpr int D      = 64;
constexpr int N      = 128;
constexpr int NSTEPS = 16;

// ---------------- device scratch (no allocations allowed) ----------------
__device__ __align__(16) float g_R[NSTEPS][D * D];  // [s][i*64+a] = R_{15-s}[a][i]
__device__ __align__(16) float g_X[NSTEPS][N * D];  // x_s, s = 0..15

// KPREP: direct row-wise simulation of BOTH systems in one launch.
//   rows 0..127   : state rows (x0, v0)            -> g_X[t], traj frames
//   rows 128..191 : propagator rows a = row-128,
//                   X0 = dt^2*e_a, V0 = dt*e_a     -> X_k = R_k, stored transposed
// One warp per row; lane owns 2 columns; M columns live in registers.
// M[k][c] = W[c][k] - delta(k,c)  (row-vector convention: f = x*M).
__global__ void __launch_bounds__(128) kprep(const float* __restrict__ x0,
                                             const float* __restrict__ v0,
                                             const float* __restrict__ W,
                                             float* __restrict__ out) {
    __shared__ float sX[4][D];
    const int tid = threadIdx.x;
    const int w   = tid >> 5;                  // warp = local row
    const int l   = tid & 31;
    const int row = blockIdx.x * 4 + w;        // 0..191
    const int c0  = 2 * l;
    const float dt = 0.01f;
    const bool is_state = (row < N);
    const int a = row - N;                     // propagator row index (if !is_state)

    // Load this lane's two M columns into registers (fully unrolled).
    float mA[D], mB[D];
    {
        const float4* wa = (const float4*)(W + (size_t)c0 * D);
        const float4* wb = (const float4*)(W + (size_t)(c0 + 1) * D);
#pragma unroll
        for (int q = 0; q < 16; q++) {
            float4 va = wa[q], vb = wb[q];
            const int k = 4 * q;
            mA[k+0] = va.x - ((k+0) == c0     ? 1.0f : 0.0f);
            mA[k+1] = va.y - ((k+1) == c0     ? 1.0f : 0.0f);
            mA[k+2] = va.z - ((k+2) == c0     ? 1.0f : 0.0f);
            mA[k+3] = va.w - ((k+3) == c0     ? 1.0f : 0.0f);
            mB[k+0] = vb.x - ((k+0) == c0 + 1 ? 1.0f : 0.0f);
            mB[k+1] = vb.y - ((k+1) == c0 + 1 ? 1.0f : 0.0f);
            mB[k+2] = vb.z - ((k+2) == c0 + 1 ? 1.0f : 0.0f);
            mB[k+3] = vb.w - ((k+3) == c0 + 1 ? 1.0f : 0.0f);
        }
    }

    // Initial state for this lane's two columns.
    float2 xl, vl;
    if (is_state) {
        xl = *(const float2*)(x0 + (size_t)row * D + c0);
        vl = *(const float2*)(v0 + (size_t)row * D + c0);
    } else {
        xl = make_float2(c0 == a ? dt * dt : 0.0f, (c0 + 1) == a ? dt * dt : 0.0f);
        vl = make_float2(c0 == a ? dt      : 0.0f, (c0 + 1) == a ? dt      : 0.0f);
    }

    // t = 0 outputs.
    if (is_state) {
        *(float2*)&g_X[0][row * D + c0] = xl;                 // x_0
        *(float2*)(out + (size_t)row * D + c0) = xl;          // traj frame 0
    } else {
        g_R[15][c0 * D + a]       = xl.x;                     // R_0 transposed
        g_R[15][(c0 + 1) * D + a] = xl.y;
    }

    *(float2*)&sX[w][c0] = xl;
    __syncwarp();

#pragma unroll 1
    for (int t = 1; t <= NSTEPS; t++) {
        // Two interleaved accumulator pairs: halves the serial FMA chain.
        float2 y0 = make_float2(0.0f, 0.0f);
        float2 y1 = make_float2(0.0f, 0.0f);
#pragma unroll
        for (int k = 0; k < D; k += 2) {
            float xk0 = sX[w][k], xk1 = sX[w][k + 1];
            y0.x += xk0 * mA[k];     y0.y += xk0 * mB[k];
            y1.x += xk1 * mA[k + 1]; y1.y += xk1 * mB[k + 1];
        }
        float2 y = make_float2(y0.x + y1.x, y0.y + y1.y);
        vl.x += dt * y.x;  vl.y += dt * y.y;
        xl.x += dt * vl.x; xl.y += dt * vl.y;
        __syncwarp();
        *(float2*)&sX[w][c0] = xl;
        __syncwarp();

        if (is_state) {
            if (t < NSTEPS)
                *(float2*)&g_X[t][row * D + c0] = xl;
            if ((t & 3) == 0) {
                float* o = out + (size_t)(t >> 2) * (N * D) + (size_t)row * D + c0;
                *(float2*)o = xl;
            }
        } else if (t < NSTEPS) {
            g_R[15 - t][c0 * D + a]       = xl.x;
            g_R[15 - t][(c0 + 1) * D + a] = xl.y;
        }
    }
}

__device__ __forceinline__ unsigned long long dup2(float f) {
    unsigned long long r;
    asm("mov.b64 %0, {%1, %1};" : "=l"(r) : "r"(__float_as_uint(f)));
    return r;
}

// K4: jac[n][i][a][b] = sum_s g_R[s][i][a] * g_X[s][n][b].
// Block covers (2 n) x (2 i) x 64a x 64b = 16384 outputs; thread does an 8x8
// tile using packed fma.rn.f32x2. R is staged in smem pre-duplicated into both
// b64 halves, so the inner loop is pure LDS.128 + FFMA2 (no movs). 2 CTAs/SM
// (NOT 3 — the 85-reg cap at occ 3 forces spills/remat, measured regression).
__global__ void __launch_bounds__(256, 2) k4_jac(float* __restrict__ jac) {
    __shared__ __align__(16) unsigned long long sR2[NSTEPS][2][D];  // 16 KB
    __shared__ __align__(16) float sX[NSTEPS][2][D];                //  8 KB
    const int tid = threadIdx.x, bid = blockIdx.x;
    const int n0 = (bid >> 5) << 1;   // 0,2,..,126
    const int i0 = (bid & 31) << 1;   // 0,2,..,62

    // Fill: 512 float4 of X; R duplicated into b64 halves.
#pragma unroll
    for (int v = tid; v < 512; v += 256) {
        const int s  = v >> 5;
        const int il = (v >> 4) & 1;
        const int aa = (v & 15) << 2;
        float4 x = *(const float4*)&g_X[s][(n0 + il) * D + aa];
        float4 r = *(const float4*)&g_R[s][(i0 + il) * D + aa];
        *(float4*)&sX[s][il][aa] = x;
        *(ulonglong2*)&sR2[s][il][aa]     = make_ulonglong2(dup2(r.x), dup2(r.y));
        *(ulonglong2*)&sR2[s][il][aa + 2] = make_ulonglong2(dup2(r.z), dup2(r.w));
    }
    __syncthreads();

    const int nl  = (tid >> 7) & 1;
    const int il  = (tid >> 6) & 1;
    const int idx = tid & 63;
    const int a0  = (idx >> 3) << 3;
    const int b0  = (idx & 7) << 3;

    unsigned long long acc[8][4];
#pragma unroll
    for (int ia = 0; ia < 8; ia++)
#pragma unroll
        for (int jb = 0; jb < 4; jb++) acc[ia][jb] = 0ull;

#pragma unroll
    for (int s = 0; s < NSTEPS; s++) {
        // xb: 8 floats = 4 packed f32x2 (b is the packed lane pair)
        const ulonglong2 x01 = *(const ulonglong2*)&sX[s][nl][b0];
        const ulonglong2 x23 = *(const ulonglong2*)&sX[s][nl][b0 + 4];
        const unsigned long long xb[4] = {x01.x, x01.y, x23.x, x23.y};
        // ra: 8 pre-duplicated b64 values, 4 LDS.128
        const ulonglong2 r01 = *(const ulonglong2*)&sR2[s][il][a0];
        const ulonglong2 r23 = *(const ulonglong2*)&sR2[s][il][a0 + 2];
        const ulonglong2 r45 = *(const ulonglong2*)&sR2[s][il][a0 + 4];
        const ulonglong2 r67 = *(const ulonglong2*)&sR2[s][il][a0 + 6];
        const unsigned long long rr[8] = {r01.x, r01.y, r23.x, r23.y,
                                          r45.x, r45.y, r67.x, r67.y};
#pragma unroll
        for (int ia = 0; ia < 8; ia++)
#pragma unroll
            for (int jb = 0; jb < 4; jb++)
                asm("fma.rn.f32x2 %0, %1, %2, %0;"
                    : "+l"(acc[ia][jb]) : "l"(rr[ia]), "l"(xb[jb]));
    }

    const size_t base = (((size_t)(n0 + nl) * D + (i0 + il)) * D) * D;
#pragma unroll
    for (int ia = 0; ia < 8; ia++) {
        float* p = jac + base + (size_t)(a0 + ia) * D + b0;
        *(ulonglong2*)p       = make_ulonglong2(acc[ia][0], acc[ia][1]);
        *(ulonglong2*)(p + 4) = make_ulonglong2(acc[ia][2], acc[ia][3]);
    }
}

extern "C" void kernel_launch(void* const* d_in, const int* in_sizes, int n_in,
                              void* d_out, int out_size) {
    const float* x0 = (const float*)d_in[0];
    const float* v0 = (const float*)d_in[1];
    const float* W  = (const float*)d_in[2];
    float* out = (float*)d_out;
    // output = [traj (frames x N x D)] then [jac (N x D x D x D)]
    float* jac = out + ((size_t)out_size - (size_t)N * D * D * D);

    kprep<<<48, 128>>>(x0, v0, W, out);
    k4_jac<<<2048, 256>>>(jac);
}